// round 2
// baseline (speedup 1.0000x reference)
#include <cuda_runtime.h>
#include <cstdint>

#define SEQ 2048
#define NB  64
#define ID  256
#define HD  256
#define G3  768

// 805 MB scratch for precomputed input projections: [dir][t][gate(768)][b(64)]
__device__ float g_gx[(size_t)2 * SEQ * G3 * NB];
// double-buffered hidden state: [dir][parity][b*HD]
__device__ float g_h[2][2][NB * HD];
__device__ unsigned g_bar_count;
__device__ unsigned g_bar_epoch;

// ---------------------------------------------------------------- init
__global__ void init_kernel() {
    int tid = blockIdx.x * blockDim.x + threadIdx.x;
    int n = 2 * 2 * NB * HD;
    float* p = &g_h[0][0][0];
    for (int i = tid; i < n; i += blockDim.x * gridDim.x) p[i] = 0.f;
    if (blockIdx.x == 0 && threadIdx.x == 0) { g_bar_count = 0u; g_bar_epoch = 0u; }
}

// ---------------------------------------------------------------- phase 1: Gx = X*Wih^T + bih
// grid (12, 2048, 2), 256 threads. Tile 64(M=batch of one t) x 64(N=gates), K=256.
__global__ __launch_bounds__(256) void gx_kernel(
    const float* __restrict__ X,
    const float* __restrict__ Wf, const float* __restrict__ bf,
    const float* __restrict__ Wb, const float* __restrict__ bb)
{
    const int dir = blockIdx.z;
    const float* W    = dir ? Wb : Wf;
    const float* bias = dir ? bb : bf;
    const int t  = blockIdx.y;
    const int n0 = blockIdx.x * 64;

    __shared__ float As[16][68];   // [k][b]
    __shared__ float Bs[16][68];   // [k][g]
    __shared__ float Cs[64][68];   // [g][b]

    const int tid = threadIdx.x;
    const int ty = tid >> 4, tx = tid & 15;
    const int lr = tid >> 2, lc = (tid & 3) << 2;

    const float* Ab = X + (size_t)t * (NB * ID) + (size_t)lr * ID + lc;
    const float* Bb2 = W + (size_t)(n0 + lr) * ID + lc;

    float acc[4][4];
#pragma unroll
    for (int i = 0; i < 4; i++)
#pragma unroll
        for (int j = 0; j < 4; j++) acc[i][j] = 0.f;

    for (int k0 = 0; k0 < ID; k0 += 16) {
        float4 a4 = *(const float4*)(Ab + k0);
        float4 b4 = *(const float4*)(Bb2 + k0);
        As[lc + 0][lr] = a4.x; As[lc + 1][lr] = a4.y; As[lc + 2][lr] = a4.z; As[lc + 3][lr] = a4.w;
        Bs[lc + 0][lr] = b4.x; Bs[lc + 1][lr] = b4.y; Bs[lc + 2][lr] = b4.z; Bs[lc + 3][lr] = b4.w;
        __syncthreads();
#pragma unroll
        for (int k = 0; k < 16; k++) {
            float4 av = *(const float4*)&As[k][ty << 2];
            float4 bv = *(const float4*)&Bs[k][tx << 2];
            float ar[4] = {av.x, av.y, av.z, av.w};
            float br[4] = {bv.x, bv.y, bv.z, bv.w};
#pragma unroll
            for (int r = 0; r < 4; r++)
#pragma unroll
                for (int c = 0; c < 4; c++)
                    acc[r][c] = fmaf(ar[r], br[c], acc[r][c]);
        }
        __syncthreads();
    }

    // epilogue: bias add + transpose to [g][b], then coalesced store
#pragma unroll
    for (int r = 0; r < 4; r++)
#pragma unroll
        for (int c = 0; c < 4; c++)
            Cs[(tx << 2) + c][(ty << 2) + r] = acc[r][c] + __ldg(bias + n0 + (tx << 2) + c);
    __syncthreads();

    float* dst = g_gx + ((size_t)dir * SEQ + t) * ((size_t)G3 * NB) + (size_t)n0 * NB;
#pragma unroll
    for (int i = 0; i < 4; i++) {
        int g  = (tid >> 4) + (i << 4);
        int b4 = (tid & 15) << 2;
        *(float4*)(dst + g * NB + b4) = *(const float4*)&Cs[g][b4];
    }
}

// ---------------------------------------------------------------- phase 2: persistent recurrence
__device__ __forceinline__ float sigmoidf_(float x) { return 1.f / (1.f + __expf(-x)); }
__device__ __forceinline__ float tanhf_(float x) {
    float e = __expf(2.f * x);
    return 1.f - 2.f / (e + 1.f);
}

// 128 CTAs: dir(2) x bhalf(2) x hcol-block(32 of 8 cols). 256 threads: (b_local 32) x (k-chunk 8).
// k partition is interleaved: thread kc owns k in { i*32 + kc*4 + l : i=0..7, l=0..3 } (coalesced LDG).
__global__ __launch_bounds__(256, 1) void gru_kernel(
    const int* __restrict__ D,
    const float* __restrict__ Whf, const float* __restrict__ bhf,
    const float* __restrict__ Whb, const float* __restrict__ bhb,
    float* __restrict__ out)
{
    const int bid   = blockIdx.x;
    const int dir   = bid >> 6;
    const int sub   = bid & 63;
    const int bhalf = sub >> 5;
    const int hc0   = (sub & 31) << 3;

    const float* Whh = dir ? Whb : Whf;
    const float* bhh = dir ? bhb : bhf;

    __shared__ float Ws[24 * 264];   // 24 gate rows x 256 k (stride 264: pad, keeps 16B align)

    const int tid = threadIdx.x;
    for (int idx = tid; idx < 24 * 256; idx += 256) {
        int j = idx >> 8, k = idx & 255;
        int grow = (j < 8) ? (hc0 + j) : (j < 16) ? (256 + hc0 + j - 8) : (512 + hc0 + j - 16);
        Ws[j * 264 + k] = Whh[(size_t)grow * HD + k];
    }

    const int bl   = tid >> 3;        // 0..31
    const int kc   = tid & 7;         // 0..7
    const int bg   = bhalf * 32 + bl; // global batch row
    const int hcol = hc0 + kc;        // this thread's output h column

    const float bhr = __ldg(bhh + hcol);
    const float bhz = __ldg(bhh + 256 + hcol);
    const float bhn = __ldg(bhh + 512 + hcol);

    __syncthreads();

    const unsigned nb1 = gridDim.x - 1;
    float my_h = 0.f;   // this thread's own h[bg][hcol] carry

    for (int s = 0; s < SEQ; s++) {
        const int p = s & 1;
        const int t = dir ? (SEQ - 1 - s) : s;
        const float* hr = g_h[dir][p];
        float* hw = g_h[dir][1 - p];

        float m;
        if (dir == 0) m = (float)__ldg(D + t * NB + bg);
        else          m = (t == SEQ - 1) ? 0.f : (float)__ldg(D + (t + 1) * NB + bg);
        const float hsc = 1.f - m;

        const float* gx = g_gx + ((size_t)dir * SEQ + t) * ((size_t)G3 * NB);
        const float gxr = __ldg(gx + (size_t)hcol * NB + bg);
        const float gxz = __ldg(gx + (size_t)(256 + hcol) * NB + bg);
        const float gxn = __ldg(gx + (size_t)(512 + hcol) * NB + bg);

        // load this row's masked h slice into registers (bypass L1: written by other SMs)
        float4 h4[8];
        const float* hpb = hr + bg * HD;
#pragma unroll
        for (int i = 0; i < 8; i++) {
            float4 v = __ldcg((const float4*)(hpb + i * 32 + kc * 4));
            v.x *= hsc; v.y *= hsc; v.z *= hsc; v.w *= hsc;
            h4[i] = v;
        }
        const float hself = my_h * hsc;

        float acc[24];
#pragma unroll
        for (int j = 0; j < 24; j++) acc[j] = 0.f;

        const float* wb = Ws + kc * 4;
#pragma unroll
        for (int i = 0; i < 8; i++) {
            const float4 hv = h4[i];
#pragma unroll
            for (int j = 0; j < 24; j++) {
                const float4 w = *(const float4*)(wb + j * 264 + i * 32);
                acc[j] = fmaf(hv.x, w.x, acc[j]);
                acc[j] = fmaf(hv.y, w.y, acc[j]);
                acc[j] = fmaf(hv.z, w.z, acc[j]);
                acc[j] = fmaf(hv.w, w.w, acc[j]);
            }
        }

        // reduce the 8-way k split (lanes kc=0..7 are consecutive)
#pragma unroll
        for (int j = 0; j < 24; j++) {
            float v = acc[j];
            v += __shfl_xor_sync(0xffffffffu, v, 1);
            v += __shfl_xor_sync(0xffffffffu, v, 2);
            v += __shfl_xor_sync(0xffffffffu, v, 4);
            acc[j] = v;
        }

        // pick this thread's 3 gate sums without dynamic register indexing
        float ghr = 0.f, ghz = 0.f, ghn = 0.f;
#pragma unroll
        for (int j = 0; j < 8; j++)
            if (kc == j) { ghr = acc[j]; ghz = acc[8 + j]; ghn = acc[16 + j]; }

        const float r = sigmoidf_(gxr + ghr + bhr);
        const float z = sigmoidf_(gxz + ghz + bhz);
        const float n = tanhf_(gxn + r * (ghn + bhn));
        const float hnew = (1.f - z) * n + z * hself;
        my_h = hnew;

        __stcg(hw + bg * HD + hcol, hnew);
        out[((size_t)t * NB + bg) * (2 * HD) + dir * HD + hcol] = hnew;

        // ---- grid barrier (epoch-based, counters reset by init kernel each launch)
        __threadfence();
        __syncthreads();
        if (tid == 0) {
            const unsigned target = (unsigned)(s + 1);
            unsigned arr = atomicAdd(&g_bar_count, 1u);
            if (arr == nb1) {
                atomicExch(&g_bar_count, 0u);
                __threadfence();
                atomicAdd(&g_bar_epoch, 1u);
            } else {
                volatile unsigned* ep = &g_bar_epoch;
                while (*ep < target) { }
            }
        }
        __syncthreads();
        __threadfence();
    }
}

// ---------------------------------------------------------------- launch
extern "C" void kernel_launch(void* const* d_in, const int* in_sizes, int n_in,
                              void* d_out, int out_size) {
    (void)in_sizes; (void)n_in; (void)out_size;
    const float* X     = (const float*)d_in[0];
    const int*   D     = (const int*)d_in[1];
    const float* Wih_f = (const float*)d_in[2];
    const float* Whh_f = (const float*)d_in[3];
    const float* bih_f = (const float*)d_in[4];
    const float* bhh_f = (const float*)d_in[5];
    const float* Wih_b = (const float*)d_in[6];
    const float* Whh_b = (const float*)d_in[7];
    const float* bih_b = (const float*)d_in[8];
    const float* bhh_b = (const float*)d_in[9];
    float* out = (float*)d_out;

    init_kernel<<<16, 256>>>();
    dim3 g1(G3 / 64, SEQ, 2);
    gx_kernel<<<g1, 256>>>(X, Wih_f, bih_f, Wih_b, bih_b);
    gru_kernel<<<128, 256>>>(D, Whh_f, bhh_f, Whh_b, bhh_b, out);
}

// round 4
// speedup vs baseline: 1.1821x; 1.1821x over previous
#include <cuda_runtime.h>
#include <cstdint>

#define SEQ 2048
#define NB  64
#define ID  256
#define HD  256
#define G3  768

using u64 = unsigned long long;

// ---------------------------------------------------------------- f32x2 helpers
__device__ __forceinline__ u64 ffma2(u64 a, u64 b, u64 c) {
    u64 d; asm("fma.rn.f32x2 %0, %1, %2, %3;" : "=l"(d) : "l"(a), "l"(b), "l"(c)); return d;
}
__device__ __forceinline__ u64 fmul2(u64 a, u64 b) {
    u64 d; asm("mul.rn.f32x2 %0, %1, %2;" : "=l"(d) : "l"(a), "l"(b)); return d;
}
__device__ __forceinline__ u64 pack2(float lo, float hi) {
    u64 d; asm("mov.b64 %0, {%1, %2};" : "=l"(d) : "f"(lo), "f"(hi)); return d;
}
__device__ __forceinline__ float2 unpack2(u64 v) {
    float2 r; asm("mov.b64 {%0, %1}, %2;" : "=f"(r.x), "=f"(r.y) : "l"(v)); return r;
}

// ---------------------------------------------------------------- sync helpers
__device__ __forceinline__ void redAddRelease(unsigned* p, unsigned v) {
    asm volatile("red.add.release.gpu.global.u32 [%0], %1;" :: "l"(p), "r"(v) : "memory");
}
__device__ __forceinline__ unsigned ldAcquire(const unsigned* p) {
    unsigned v; asm volatile("ld.acquire.gpu.global.u32 %0, [%1];" : "=r"(v) : "l"(p) : "memory"); return v;
}

// 805 MB scratch: [dir][t][gate(768)][b(64)]
__device__ float g_gx[(size_t)2 * SEQ * G3 * NB];
// double-buffered hidden state: [dir][parity][b*HD]
__device__ float g_h[2][2][NB * HD];
// 4 barrier groups (dir x bhalf), monotonic counters, 128B apart
__device__ unsigned g_bar[4 * 32];

// ---------------------------------------------------------------- init
__global__ void init_kernel() {
    int tid = blockIdx.x * blockDim.x + threadIdx.x;
    int n = 2 * 2 * NB * HD;
    float* p = &g_h[0][0][0];
    for (int i = tid; i < n; i += blockDim.x * gridDim.x) p[i] = 0.f;
    if (blockIdx.x == 0 && threadIdx.x < 4 * 32) g_bar[threadIdx.x] = 0u;
}

// ---------------------------------------------------------------- phase 1: Gx = X*Wih^T + bih
// grid (12, 2048, 2), 256 threads. Tile 64(batch) x 64(gates), K=256. f32x2 microkernel.
__global__ __launch_bounds__(256) void gx_kernel(
    const float* __restrict__ X,
    const float* __restrict__ Wf, const float* __restrict__ bf,
    const float* __restrict__ Wb, const float* __restrict__ bb)
{
    const int dir = blockIdx.z;
    const float* W    = dir ? Wb : Wf;
    const float* bias = dir ? bb : bf;
    const int t  = blockIdx.y;
    const int n0 = blockIdx.x * 64;

    __shared__ __align__(16) float As[16][68];   // [k][b]
    __shared__ __align__(16) float Bs[16][68];   // [k][g]
    __shared__ __align__(16) float Cs[64][68];   // [g][b]

    const int tid = threadIdx.x;
    const int ty = tid >> 4, tx = tid & 15;
    const int lr = tid >> 2, lc = (tid & 3) << 2;

    const float* Ab  = X + (size_t)t * (NB * ID) + (size_t)lr * ID + lc;
    const float* Bb2 = W + (size_t)(n0 + lr) * ID + lc;

    u64 acc2[4][2];
#pragma unroll
    for (int i = 0; i < 4; i++) { acc2[i][0] = 0ull; acc2[i][1] = 0ull; }

    for (int k0 = 0; k0 < ID; k0 += 16) {
        float4 a4 = *(const float4*)(Ab + k0);
        float4 b4 = *(const float4*)(Bb2 + k0);
        As[lc + 0][lr] = a4.x; As[lc + 1][lr] = a4.y; As[lc + 2][lr] = a4.z; As[lc + 3][lr] = a4.w;
        Bs[lc + 0][lr] = b4.x; Bs[lc + 1][lr] = b4.y; Bs[lc + 2][lr] = b4.z; Bs[lc + 3][lr] = b4.w;
        __syncthreads();
#pragma unroll
        for (int k = 0; k < 16; k++) {
            float4 av = *(const float4*)&As[k][ty << 2];
            float4 bv = *(const float4*)&Bs[k][tx << 2];
            const u64 b01 = pack2(bv.x, bv.y);
            const u64 b23 = pack2(bv.z, bv.w);
            float ar[4] = {av.x, av.y, av.z, av.w};
#pragma unroll
            for (int r = 0; r < 4; r++) {
                const u64 aa = pack2(ar[r], ar[r]);
                acc2[r][0] = ffma2(aa, b01, acc2[r][0]);
                acc2[r][1] = ffma2(aa, b23, acc2[r][1]);
            }
        }
        __syncthreads();
    }

    // epilogue: bias add + transpose to [g][b], then coalesced store
#pragma unroll
    for (int r = 0; r < 4; r++) {
        float2 c01 = unpack2(acc2[r][0]);
        float2 c23 = unpack2(acc2[r][1]);
        float cc[4] = {c01.x, c01.y, c23.x, c23.y};
#pragma unroll
        for (int c = 0; c < 4; c++)
            Cs[(tx << 2) + c][(ty << 2) + r] = cc[c] + __ldg(bias + n0 + (tx << 2) + c);
    }
    __syncthreads();

    float* dst = g_gx + ((size_t)dir * SEQ + t) * ((size_t)G3 * NB) + (size_t)n0 * NB;
#pragma unroll
    for (int i = 0; i < 4; i++) {
        int g  = (tid >> 4) + (i << 4);
        int b4 = (tid & 15) << 2;
        *(float4*)(dst + g * NB + b4) = *(const float4*)&Cs[g][b4];
    }
}

// ---------------------------------------------------------------- phase 2: persistent recurrence
__device__ __forceinline__ float sigmoidf_(float x) { return 1.f / (1.f + __expf(-x)); }
__device__ __forceinline__ float tanhf_(float x) {
    float e = __expf(2.f * x);
    return 1.f - 2.f / (e + 1.f);
}

// 128 CTAs: dir(2) x bhalf(2) x hcol-block(32 of 8 cols). 256 threads: (b_local 32) x (k-chunk 8).
__global__ __launch_bounds__(256, 1) void gru_kernel(
    const int* __restrict__ D,
    const float* __restrict__ Whf, const float* __restrict__ bhf,
    const float* __restrict__ Whb, const float* __restrict__ bhb,
    float* __restrict__ out)
{
    const int bid   = blockIdx.x;
    const int dir   = bid >> 6;
    const int sub   = bid & 63;
    const int bhalf = sub >> 5;
    const int hc0   = (sub & 31) << 3;
    const int grp   = bid >> 5;                 // barrier group (dir,bhalf)
    unsigned* bar   = &g_bar[grp * 32];

    const float* Whh = dir ? Whb : Whf;
    const float* bhh = dir ? bhb : bhf;

    __shared__ __align__(16) float Ws[24 * 264];   // 24 gate rows x 256 k (padded stride)

    const int tid = threadIdx.x;
    for (int idx = tid; idx < 24 * 256; idx += 256) {
        int j = idx >> 8, k = idx & 255;
        int grow = (j < 8) ? (hc0 + j) : (j < 16) ? (256 + hc0 + j - 8) : (512 + hc0 + j - 16);
        Ws[j * 264 + k] = Whh[(size_t)grow * HD + k];
    }

    const int bl   = tid >> 3;        // 0..31
    const int kc   = tid & 7;         // 0..7
    const int bg   = bhalf * 32 + bl; // global batch row
    const int hcol = hc0 + kc;

    const float bhr = __ldg(bhh + hcol);
    const float bhz = __ldg(bhh + 256 + hcol);
    const float bhn = __ldg(bhh + 512 + hcol);

    __syncthreads();

    float my_h = 0.f;

    // prefetch step 0
    float pf_gxr, pf_gxz, pf_gxn, pf_m;
    {
        const int t0 = dir ? (SEQ - 1) : 0;
        const float* gx = g_gx + ((size_t)dir * SEQ + t0) * ((size_t)G3 * NB);
        pf_gxr = __ldg(gx + (size_t)hcol * NB + bg);
        pf_gxz = __ldg(gx + (size_t)(256 + hcol) * NB + bg);
        pf_gxn = __ldg(gx + (size_t)(512 + hcol) * NB + bg);
        if (dir == 0) pf_m = (float)__ldg(D + t0 * NB + bg);
        else          pf_m = 0.f;   // t0 == SEQ-1
    }

    for (int s = 0; s < SEQ; s++) {
        const int p = s & 1;
        const int t = dir ? (SEQ - 1 - s) : s;
        const float* hr = g_h[dir][p];
        float* hw = g_h[dir][1 - p];

        // consume prefetched values
        const float gxr = pf_gxr, gxz = pf_gxz, gxn = pf_gxn;
        const float hsc = 1.f - pf_m;
        const u64 hsc2 = pack2(hsc, hsc);

        // issue prefetch for s+1 (independent of barrier / h state)
        if (s + 1 < SEQ) {
            const int t2 = dir ? (SEQ - 2 - s) : (s + 1);
            const float* gx2 = g_gx + ((size_t)dir * SEQ + t2) * ((size_t)G3 * NB);
            pf_gxr = __ldg(gx2 + (size_t)hcol * NB + bg);
            pf_gxz = __ldg(gx2 + (size_t)(256 + hcol) * NB + bg);
            pf_gxn = __ldg(gx2 + (size_t)(512 + hcol) * NB + bg);
            if (dir == 0) pf_m = (float)__ldg(D + t2 * NB + bg);
            else          pf_m = (t2 == SEQ - 1) ? 0.f : (float)__ldg(D + (t2 + 1) * NB + bg);
        }

        // load masked h slice (L2, written by peer SMs last step)
        u64 hp[16];
        const float* hpb = hr + bg * HD;
#pragma unroll
        for (int i = 0; i < 8; i++) {
            float4 v = __ldcg((const float4*)(hpb + i * 32 + kc * 4));
            hp[2 * i + 0] = fmul2(pack2(v.x, v.y), hsc2);
            hp[2 * i + 1] = fmul2(pack2(v.z, v.w), hsc2);
        }
        const float hself = my_h * hsc;

        u64 acc2[24];
#pragma unroll
        for (int j = 0; j < 24; j++) acc2[j] = 0ull;

        const float* wb = Ws + kc * 4;
#pragma unroll
        for (int i = 0; i < 8; i++) {
            const u64 ha = hp[2 * i], hb2 = hp[2 * i + 1];
#pragma unroll
            for (int j = 0; j < 24; j++) {
                const ulonglong2 w = *(const ulonglong2*)(wb + j * 264 + i * 32);
                acc2[j] = ffma2(ha,  w.x, acc2[j]);
                acc2[j] = ffma2(hb2, w.y, acc2[j]);
            }
        }

        // fold halves + 8-way k-split shfl reduce
        float acc[24];
#pragma unroll
        for (int j = 0; j < 24; j++) {
            float2 f = unpack2(acc2[j]);
            float v = f.x + f.y;
            v += __shfl_xor_sync(0xffffffffu, v, 1);
            v += __shfl_xor_sync(0xffffffffu, v, 2);
            v += __shfl_xor_sync(0xffffffffu, v, 4);
            acc[j] = v;
        }

        float ghr = 0.f, ghz = 0.f, ghn = 0.f;
#pragma unroll
        for (int j = 0; j < 8; j++)
            if (kc == j) { ghr = acc[j]; ghz = acc[8 + j]; ghn = acc[16 + j]; }

        const float r = sigmoidf_(gxr + ghr + bhr);
        const float z = sigmoidf_(gxz + ghz + bhz);
        const float n = tanhf_(gxn + r * (ghn + bhn));
        const float hnew = (1.f - z) * n + z * hself;
        my_h = hnew;

        __stcg(hw + bg * HD + hcol, hnew);
        out[((size_t)t * NB + bg) * (2 * HD) + dir * HD + hcol] = hnew;

        // ---- 32-CTA group barrier: monotonic release/acquire counter
        __syncthreads();
        if (tid == 0) {
            redAddRelease(bar, 1u);
            const unsigned target = 32u * (unsigned)(s + 1);
            while (ldAcquire(bar) < target) { }
        }
        __syncthreads();
    }
}

// ---------------------------------------------------------------- launch
extern "C" void kernel_launch(void* const* d_in, const int* in_sizes, int n_in,
                              void* d_out, int out_size) {
    (void)in_sizes; (void)n_in; (void)out_size;
    const float* X     = (const float*)d_in[0];
    const int*   D     = (const int*)d_in[1];
    const float* Wih_f = (const float*)d_in[2];
    const float* Whh_f = (const float*)d_in[3];
    const float* bih_f = (const float*)d_in[4];
    const float* bhh_f = (const float*)d_in[5];
    const float* Wih_b = (const float*)d_in[6];
    const float* Whh_b = (const float*)d_in[7];
    const float* bih_b = (const float*)d_in[8];
    const float* bhh_b = (const float*)d_in[9];
    float* out = (float*)d_out;

    init_kernel<<<16, 256>>>();
    dim3 g1(G3 / 64, SEQ, 2);
    gx_kernel<<<g1, 256>>>(X, Wih_f, bih_f, Wih_b, bih_b);
    gru_kernel<<<128, 256>>>(D, Whh_f, bhh_f, Whh_b, bhh_b, out);
}

// round 8
// speedup vs baseline: 1.4817x; 1.2534x over previous
#include <cuda_runtime.h>
#include <cstdint>

#define SEQ 2048
#define NB  64
#define ID  256
#define HD  256
#define G3  768
#define SW  264   // Ws row stride in floats

using u64 = unsigned long long;

// ---------------------------------------------------------------- f32x2 helpers
__device__ __forceinline__ u64 ffma2(u64 a, u64 b, u64 c) {
    u64 d; asm("fma.rn.f32x2 %0, %1, %2, %3;" : "=l"(d) : "l"(a), "l"(b), "l"(c)); return d;
}
__device__ __forceinline__ u64 fmul2(u64 a, u64 b) {
    u64 d; asm("mul.rn.f32x2 %0, %1, %2;" : "=l"(d) : "l"(a), "l"(b)); return d;
}
__device__ __forceinline__ u64 pack2(float lo, float hi) {
    u64 d; asm("mov.b64 %0, {%1, %2};" : "=l"(d) : "f"(lo), "f"(hi)); return d;
}
__device__ __forceinline__ float2 unpack2(u64 v) {
    float2 r; asm("mov.b64 {%0, %1}, %2;" : "=f"(r.x), "=f"(r.y) : "l"(v)); return r;
}

// ---------------------------------------------------------------- sync helpers
__device__ __forceinline__ void redAddRelease(unsigned* p, unsigned v) {
    asm volatile("red.add.release.gpu.global.u32 [%0], %1;" :: "l"(p), "r"(v) : "memory");
}
__device__ __forceinline__ unsigned ldAcquire(const unsigned* p) {
    unsigned v; asm volatile("ld.acquire.gpu.global.u32 %0, [%1];" : "=r"(v) : "l"(p) : "memory"); return v;
}

__device__ __forceinline__ float pick4(float4 v, int r) {
    float lo = (r & 1) ? v.y : v.x;
    float hi = (r & 1) ? v.w : v.z;
    return (r & 2) ? hi : lo;
}

// 805 MB scratch: [dir][t][gate(768)][b(64)]
__device__ float g_gx[(size_t)2 * SEQ * G3 * NB];
// double-buffered hidden state: [dir][parity][b*HD]
__device__ float g_h[2][2][NB * HD];
// 4 barrier groups (dir x bhalf), monotonic counters, 128B apart
__device__ unsigned g_bar[4 * 32];

// ---------------------------------------------------------------- init
__global__ void init_kernel() {
    int tid = blockIdx.x * blockDim.x + threadIdx.x;
    int n = 2 * 2 * NB * HD;
    float* p = &g_h[0][0][0];
    for (int i = tid; i < n; i += blockDim.x * gridDim.x) p[i] = 0.f;
    if (blockIdx.x == 0 && threadIdx.x < 4 * 32) g_bar[threadIdx.x] = 0u;
}

// ---------------------------------------------------------------- phase 1: Gx = X*Wih^T + bih
__global__ __launch_bounds__(256) void gx_kernel(
    const float* __restrict__ X,
    const float* __restrict__ Wf, const float* __restrict__ bf,
    const float* __restrict__ Wb, const float* __restrict__ bb)
{
    const int dir = blockIdx.z;
    const float* W    = dir ? Wb : Wf;
    const float* bias = dir ? bb : bf;
    const int t  = blockIdx.y;
    const int n0 = blockIdx.x * 64;

    __shared__ __align__(16) float As[16][68];
    __shared__ __align__(16) float Bs[16][68];
    __shared__ __align__(16) float Cs[64][68];

    const int tid = threadIdx.x;
    const int ty = tid >> 4, tx = tid & 15;
    const int lr = tid >> 2, lc = (tid & 3) << 2;

    const float* Ab  = X + (size_t)t * (NB * ID) + (size_t)lr * ID + lc;
    const float* Bb2 = W + (size_t)(n0 + lr) * ID + lc;

    u64 acc2[4][2];
#pragma unroll
    for (int i = 0; i < 4; i++) { acc2[i][0] = 0ull; acc2[i][1] = 0ull; }

    for (int k0 = 0; k0 < ID; k0 += 16) {
        float4 a4 = *(const float4*)(Ab + k0);
        float4 b4 = *(const float4*)(Bb2 + k0);
        As[lc + 0][lr] = a4.x; As[lc + 1][lr] = a4.y; As[lc + 2][lr] = a4.z; As[lc + 3][lr] = a4.w;
        Bs[lc + 0][lr] = b4.x; Bs[lc + 1][lr] = b4.y; Bs[lc + 2][lr] = b4.z; Bs[lc + 3][lr] = b4.w;
        __syncthreads();
#pragma unroll
        for (int k = 0; k < 16; k++) {
            float4 av = *(const float4*)&As[k][ty << 2];
            float4 bv = *(const float4*)&Bs[k][tx << 2];
            const u64 b01 = pack2(bv.x, bv.y);
            const u64 b23 = pack2(bv.z, bv.w);
            float ar[4] = {av.x, av.y, av.z, av.w};
#pragma unroll
            for (int r = 0; r < 4; r++) {
                const u64 aa = pack2(ar[r], ar[r]);
                acc2[r][0] = ffma2(aa, b01, acc2[r][0]);
                acc2[r][1] = ffma2(aa, b23, acc2[r][1]);
            }
        }
        __syncthreads();
    }

#pragma unroll
    for (int r = 0; r < 4; r++) {
        float2 c01 = unpack2(acc2[r][0]);
        float2 c23 = unpack2(acc2[r][1]);
        float cc[4] = {c01.x, c01.y, c23.x, c23.y};
#pragma unroll
        for (int c = 0; c < 4; c++)
            Cs[(tx << 2) + c][(ty << 2) + r] = cc[c] + __ldg(bias + n0 + (tx << 2) + c);
    }
    __syncthreads();

    float* dst = g_gx + ((size_t)dir * SEQ + t) * ((size_t)G3 * NB) + (size_t)n0 * NB;
#pragma unroll
    for (int i = 0; i < 4; i++) {
        int g  = (tid >> 4) + (i << 4);
        int b4 = (tid & 15) << 2;
        *(float4*)(dst + g * NB + b4) = *(const float4*)&Cs[g][b4];
    }
}

// ---------------------------------------------------------------- phase 2: persistent recurrence
__device__ __forceinline__ float sigmoidf_(float x) { return 1.f / (1.f + __expf(-x)); }
__device__ __forceinline__ float tanhf_(float x) {
    float e = __expf(2.f * x);
    return 1.f - 2.f / (e + 1.f);
}

// 128 CTAs: dir(2) x bhalf(2) x hc-block(32 of 8 cols).
// 256 threads = (jg:2) x (bl8:8, 4 rows each) x (kc:16, 16 k each).
// Each thread: 4 batch rows x 12 gate rows x 16 k = 768 FMA, weights reused 4x.
__global__ __launch_bounds__(256, 1) void gru_kernel(
    const int* __restrict__ D,
    const float* __restrict__ Whf, const float* __restrict__ bhf,
    const float* __restrict__ Whb, const float* __restrict__ bhb,
    float* __restrict__ out)
{
    const int bid   = blockIdx.x;
    const int dir   = bid >> 6;
    const int sub   = bid & 63;
    const int bhalf = sub >> 5;
    const int hc0   = (sub & 31) << 3;
    const int grp   = bid >> 5;
    unsigned* bar   = &g_bar[grp * 32];

    const float* Whh = dir ? Whb : Whf;
    const float* bhh = dir ? bhb : bhf;

    __shared__ __align__(16) float Ws[24 * SW];   // rows: g*8 + hl (hl = hcol-hc0)

    const int tid = threadIdx.x;
    for (int idx = tid; idx < 24 * 256; idx += 256) {
        int r = idx >> 8, k = idx & 255;
        int g = r >> 3, hl = r & 7;
        Ws[r * SW + k] = Whh[(size_t)(g * 256 + hc0 + hl) * HD + k];
    }

    const int jg   = tid >> 7;          // 0..1
    const int bl8  = (tid >> 4) & 7;    // 0..7
    const int kc   = tid & 15;          // 0..15
    const int myq  = kc & 3;
    const int myrb = kc >> 2;
    const int rowbase = bhalf * 32 + bl8 * 4;     // first of this thread's 4 rows
    const int b_own   = rowbase + myrb;
    const int hcol    = hc0 + jg * 4 + myq;

    const float bhr = __ldg(bhh + hcol);
    const float bhz = __ldg(bhh + 256 + hcol);
    const float bhn = __ldg(bhh + 512 + hcol);

    __syncthreads();

    float my_h = 0.f;

    // prefetch step 0: gx for own (b,hcol) + mask int4 for 4 rows
    float pf_gxr, pf_gxz, pf_gxn;
    int4 pf_md;
    {
        const int t0 = dir ? (SEQ - 1) : 0;
        const float* gx = g_gx + ((size_t)dir * SEQ + t0) * ((size_t)G3 * NB);
        pf_gxr = __ldg(gx + (size_t)hcol * NB + b_own);
        pf_gxz = __ldg(gx + (size_t)(256 + hcol) * NB + b_own);
        pf_gxn = __ldg(gx + (size_t)(512 + hcol) * NB + b_own);
        if (dir == 0) pf_md = *(const int4*)(D + t0 * NB + rowbase);
        else          pf_md = make_int4(0, 0, 0, 0);
    }

    for (int s = 0; s < SEQ; s++) {
        const int p = s & 1;
        const int t = dir ? (SEQ - 1 - s) : s;
        const float* hr = g_h[dir][p];
        float* hw = g_h[dir][1 - p];

        const float gxr = pf_gxr, gxz = pf_gxz, gxn = pf_gxn;
        const float4 hscv = make_float4(1.f - (float)pf_md.x, 1.f - (float)pf_md.y,
                                        1.f - (float)pf_md.z, 1.f - (float)pf_md.w);

        // prefetch s+1 (independent of barrier / h)
        if (s + 1 < SEQ) {
            const int t2 = dir ? (SEQ - 2 - s) : (s + 1);
            const float* gx2 = g_gx + ((size_t)dir * SEQ + t2) * ((size_t)G3 * NB);
            pf_gxr = __ldg(gx2 + (size_t)hcol * NB + b_own);
            pf_gxz = __ldg(gx2 + (size_t)(256 + hcol) * NB + b_own);
            pf_gxn = __ldg(gx2 + (size_t)(512 + hcol) * NB + b_own);
            if (dir == 0) pf_md = *(const int4*)(D + t2 * NB + rowbase);
            else          pf_md = (t2 == SEQ - 1) ? make_int4(0, 0, 0, 0)
                                                  : *(const int4*)(D + (t2 + 1) * NB + rowbase);
        }

        // load masked h: hreg[e][i] = chunk (i^myrb) of row (rowbase + (myrb^e)), scaled
        u64 hreg[4][4][2];
#pragma unroll
        for (int e = 0; e < 4; e++) {
            const int re = myrb ^ e;
            const float hs = pick4(hscv, re);
            const u64 hs2 = pack2(hs, hs);
            const float* rowp = hr + (size_t)(rowbase + re) * HD + kc * 16;
#pragma unroll
            for (int i = 0; i < 4; i++) {
                const int c = i ^ myrb;
                float4 v = __ldcg((const float4*)(rowp + c * 4));
                hreg[e][i][0] = fmul2(pack2(v.x, v.y), hs2);
                hreg[e][i][1] = fmul2(pack2(v.z, v.w), hs2);
            }
        }
        const float hself = my_h * pick4(hscv, myrb);

        // acc2[g][d]: partial for target lane (kc^d); d = e*4 + dq
        u64 acc2[3][16];
#pragma unroll
        for (int g = 0; g < 3; g++)
#pragma unroll
            for (int d = 0; d < 16; d++) acc2[g][d] = 0ull;

        const float* wkb = Ws + jg * 4 * SW + kc * 16;
#pragma unroll
        for (int i = 0; i < 4; i++) {
            const int koff = (i ^ myrb) * 4;
#pragma unroll
            for (int g = 0; g < 3; g++) {
#pragma unroll
                for (int dq = 0; dq < 4; dq++) {
                    const ulonglong2 w = *(const ulonglong2*)(wkb + (g * 8 + (myq ^ dq)) * SW + koff);
#pragma unroll
                    for (int e = 0; e < 4; e++) {
                        acc2[g][e * 4 + dq] = ffma2(hreg[e][i][0], w.x, acc2[g][e * 4 + dq]);
                        acc2[g][e * 4 + dq] = ffma2(hreg[e][i][1], w.y, acc2[g][e * 4 + dq]);
                    }
                }
            }
        }

        // fold f32x2 halves, then reduce-scatter over the 16 kc lanes (45 shfl)
        float gh[3];
#pragma unroll
        for (int g = 0; g < 3; g++) {
            float tg[16];
#pragma unroll
            for (int d = 0; d < 16; d++) {
                float2 f = unpack2(acc2[g][d]);
                tg[d] = f.x + f.y;
            }
#pragma unroll
            for (int m = 8; m >= 1; m >>= 1) {
#pragma unroll
                for (int d = 0; d < 8; d++) {
                    if (d < m)
                        tg[d] += __shfl_xor_sync(0xffffffffu, tg[d + m], m);
                }
            }
            gh[g] = tg[0];
        }

        const float r = sigmoidf_(gxr + gh[0] + bhr);
        const float z = sigmoidf_(gxz + gh[1] + bhz);
        const float n = tanhf_(gxn + r * (gh[2] + bhn));
        const float hnew = (1.f - z) * n + z * hself;
        my_h = hnew;

        __stcg(hw + (size_t)b_own * HD + hcol, hnew);
        out[((size_t)t * NB + b_own) * (2 * HD) + dir * HD + hcol] = hnew;

        // ---- 32-CTA group barrier: monotonic release/acquire counter
        __syncthreads();
        if (tid == 0) {
            redAddRelease(bar, 1u);
            const unsigned target = 32u * (unsigned)(s + 1);
            while (ldAcquire(bar) < target) { }
        }
        __syncthreads();
    }
}

// ---------------------------------------------------------------- launch
extern "C" void kernel_launch(void* const* d_in, const int* in_sizes, int n_in,
                              void* d_out, int out_size) {
    (void)in_sizes; (void)n_in; (void)out_size;
    const float* X     = (const float*)d_in[0];
    const int*   D     = (const int*)d_in[1];
    const float* Wih_f = (const float*)d_in[2];
    const float* Whh_f = (const float*)d_in[3];
    const float* bih_f = (const float*)d_in[4];
    const float* bhh_f = (const float*)d_in[5];
    const float* Wih_b = (const float*)d_in[6];
    const float* Whh_b = (const float*)d_in[7];
    const float* bih_b = (const float*)d_in[8];
    const float* bhh_b = (const float*)d_in[9];
    float* out = (float*)d_out;

    init_kernel<<<16, 256>>>();
    dim3 g1(G3 / 64, SEQ, 2);
    gx_kernel<<<g1, 256>>>(X, Wih_f, bih_f, Wih_b, bih_b);
    gru_kernel<<<128, 256>>>(D, Whh_f, bhh_f, Whh_b, bhh_b, out);
}